// round 6
// baseline (speedup 1.0000x reference)
#include <cuda_runtime.h>
#include <cuda_bf16.h>

#define T_LEN   4000
#define THREADS 512
#define NSEG    2       // 2 segments x 2048 elements = 4096 >= 4000

__device__ __forceinline__ float fsqrt_approx(float u) {
    float r; asm("sqrt.approx.f32 %0, %1;" : "=f"(r) : "f"(u)); return r;
}
__device__ __forceinline__ float flg2(float u) {
    float r; asm("lg2.approx.f32 %0, %1;" : "=f"(r) : "f"(u)); return r;
}
__device__ __forceinline__ float fex2(float u) {
    float r; asm("ex2.approx.f32 %0, %1;" : "=f"(r) : "f"(u)); return r;
}

__global__ __launch_bounds__(THREADS, 4)   // force <=32 regs -> 64 warps/SM
void pcen_kernel(const float* __restrict__ x, float* __restrict__ out)
{
    __shared__ float sT[32];   // (segment, warp) 128-element chunk totals
    __shared__ float sC[32];   // exclusive carries per chunk

    const float a      = 0.975f;     // 1 - S
    const float S_     = 0.025f;
    const float NALPHA = -0.98f;
    const float DELTA  = 2.0f;
    const float EPSf   = 1e-6f;
    const float DR     = 1.41421356237309515f;  // sqrt(2)

    // compile-time powers of a (constant-folded into FFMA immediates)
    const float a2 = a*a, a4 = a2*a2, a8 = a4*a4, a16 = a8*a8,
                a32 = a16*a16, a64 = a32*a32, a128 = a64*a64,
                a256 = a128*a128, a512 = a256*a256,
                a1024 = a512*a512, a2048 = a1024*a1024;

    const int tid  = threadIdx.x;
    const int lane = tid & 31, warp = tid >> 5;   // 16 warps
    const int row  = blockIdx.x;
    const float* __restrict__ xr   = x   + (size_t)row * T_LEN;
    float* __restrict__       orow = out + (size_t)row * T_LEN;

    // a^(4*lane) via bit product (exact, 5 predicated mults)
    float A4L = 1.0f;
    if (lane & 1)  A4L *= a4;
    if (lane & 2)  A4L *= a8;
    if (lane & 4)  A4L *= a16;
    if (lane & 8)  A4L *= a32;
    if (lane & 16) A4L *= a64;

    // ---- load: 2 coalesced float4 per thread, zero-pad tail ----
    float xv[8];
    #pragma unroll
    for (int j = 0; j < NSEG; j++) {
        int i = j * 2048 + tid * 4;
        float4 t4 = make_float4(0.f, 0.f, 0.f, 0.f);
        if (i < T_LEN) t4 = *reinterpret_cast<const float4*>(xr + i);
        xv[4*j+0] = t4.x; xv[4*j+1] = t4.y; xv[4*j+2] = t4.z; xv[4*j+3] = t4.w;
    }

    // ---- pass 1: serial 4-scan + 5-step constant-a Kogge-Stone per segment ----
    // b[0] = x[0] (global init), b[t] = S*x[t] otherwise
    float P[NSEG];
    #pragma unroll
    for (int j = 0; j < NSEG; j++) {
        float h = 0.f;
        #pragma unroll
        for (int k = 0; k < 4; k++) {
            float b = S_ * xv[4*j+k];
            if (j == 0 && tid == 0 && k == 0) b = xv[0];
            h = fmaf(a, h, b);
        }
        float y = h, yp;
        yp = __shfl_up_sync(0xFFFFFFFFu, y, 1);  if (lane >= 1)  y = fmaf(a4,  yp, y);
        yp = __shfl_up_sync(0xFFFFFFFFu, y, 2);  if (lane >= 2)  y = fmaf(a8,  yp, y);
        yp = __shfl_up_sync(0xFFFFFFFFu, y, 4);  if (lane >= 4)  y = fmaf(a16, yp, y);
        yp = __shfl_up_sync(0xFFFFFFFFu, y, 8);  if (lane >= 8)  y = fmaf(a32, yp, y);
        yp = __shfl_up_sync(0xFFFFFFFFu, y, 16); if (lane >= 16) y = fmaf(a64, yp, y);
        P[j] = y;
        if (lane == 31) sT[j * 16 + warp] = y;   // 128-element chunk total
    }
    __syncthreads();

    // ---- middle scan: 32 chunks in chain order c = j*16 + w (A = a^128) ----
    if (warp == 0) {
        float y = sT[lane], yp;
        yp = __shfl_up_sync(0xFFFFFFFFu, y, 1);  if (lane >= 1)  y = fmaf(a128,  yp, y);
        yp = __shfl_up_sync(0xFFFFFFFFu, y, 2);  if (lane >= 2)  y = fmaf(a256,  yp, y);
        yp = __shfl_up_sync(0xFFFFFFFFu, y, 4);  if (lane >= 4)  y = fmaf(a512,  yp, y);
        yp = __shfl_up_sync(0xFFFFFFFFu, y, 8);  if (lane >= 8)  y = fmaf(a1024, yp, y);
        yp = __shfl_up_sync(0xFFFFFFFFu, y, 16); if (lane >= 16) y = fmaf(a2048, yp, y);
        float e = __shfl_up_sync(0xFFFFFFFFu, y, 1);
        sC[lane] = (lane == 0) ? 0.f : e;       // exclusive carry per chunk
    }
    __syncthreads();

    // ---- pass 2: apply carries, seeded recurrence + pointwise PCEN, store ----
    #pragma unroll
    for (int j = 0; j < NSEG; j++) {
        float Cw = sC[j * 16 + warp];                    // carry into this warp-chunk
        float E  = __shfl_up_sync(0xFFFFFFFFu, P[j], 1); // lane-exclusive prefix
        if (lane == 0) E = 0.f;
        float sm = fmaf(A4L, Cw, E);                     // smooth just before this thread

        float r[4];
        #pragma unroll
        for (int k = 0; k < 4; k++) {
            float xk = xv[4*j+k];
            float b = S_ * xk;
            if (j == 0 && tid == 0 && k == 0) b = xk;
            sm = fmaf(a, sm, b);
            float p = fex2(NALPHA * flg2(sm + EPSf));    // (sm+eps)^-0.98
            r[k] = fsqrt_approx(fmaf(xk, p, DELTA)) - DR;
        }

        int i = j * 2048 + tid * 4;
        if (i < T_LEN)
            *reinterpret_cast<float4*>(orow + i) = make_float4(r[0], r[1], r[2], r[3]);
    }
}

extern "C" void kernel_launch(void* const* d_in, const int* in_sizes, int n_in,
                              void* d_out, int out_size)
{
    const float* x = (const float*)d_in[0];
    float* out = (float*)d_out;
    int rows = in_sizes[0] / T_LEN;   // 8192
    pcen_kernel<<<rows, THREADS>>>(x, out);
}

// round 8
// speedup vs baseline: 1.0047x; 1.0047x over previous
#include <cuda_runtime.h>
#include <cuda_bf16.h>

#define T_LEN   4000
#define THREADS 256
#define NSEG    4       // 4 segments x 1024 = 4096 >= 4000
#define NBLK    888     // 148 SMs x 6 blocks -> single wave

__device__ __forceinline__ float fsqrt_approx(float u) {
    float r; asm("sqrt.approx.f32 %0, %1;" : "=f"(r) : "f"(u)); return r;
}
__device__ __forceinline__ float flg2(float u) {
    float r; asm("lg2.approx.f32 %0, %1;" : "=f"(r) : "f"(u)); return r;
}
__device__ __forceinline__ float fex2(float u) {
    float r; asm("ex2.approx.f32 %0, %1;" : "=f"(r) : "f"(u)); return r;
}

__global__ __launch_bounds__(THREADS, 6)
void pcen_kernel(const float* __restrict__ x, float* __restrict__ out, int rows)
{
    __shared__ float sT[32];   // 128-element chunk totals (chain order c = j*8 + warp)

    const float a      = 0.975f;     // 1 - S
    const float S_     = 0.025f;
    const float NALPHA = -0.98f;
    const float DELTA  = 2.0f;
    const float EPSf   = 1e-6f;
    const float DR     = 1.41421356237309515f;  // sqrt(2)

    // compile-time powers of a
    const float a2 = a*a, a4 = a2*a2, a8 = a4*a4, a16 = a8*a8,
                a32 = a16*a16, a64 = a32*a32, a128 = a64*a64,
                a256 = a128*a128, a512 = a256*a256,
                a1024 = a512*a512, a2048 = a1024*a1024;

    const int tid  = threadIdx.x;
    const int lane = tid & 31, warp = tid >> 5;   // 8 warps

    // a^(4*lane), exact bit product
    float A4L = 1.0f;
    if (lane & 1)  A4L *= a4;
    if (lane & 2)  A4L *= a8;
    if (lane & 4)  A4L *= a16;
    if (lane & 8)  A4L *= a32;
    if (lane & 16) A4L *= a64;

    for (int row = blockIdx.x; row < rows; row += NBLK) {
        const float* __restrict__ xr   = x   + (size_t)row * T_LEN;
        float* __restrict__       orow = out + (size_t)row * T_LEN;

        // ---- load: 4 coalesced float4 per thread, zero-pad tail ----
        float xv[16];
        #pragma unroll
        for (int j = 0; j < NSEG; j++) {
            int i = j * 1024 + tid * 4;
            float4 t4 = make_float4(0.f, 0.f, 0.f, 0.f);
            if (i < T_LEN) t4 = *reinterpret_cast<const float4*>(xr + i);
            xv[4*j+0] = t4.x; xv[4*j+1] = t4.y; xv[4*j+2] = t4.z; xv[4*j+3] = t4.w;
        }

        // ---- pass 1: serial 4-scan + constant-a Kogge-Stone per segment ----
        // b[0] = x[0] (global init), b[t] = S*x[t] otherwise
        float P[NSEG];
        #pragma unroll
        for (int j = 0; j < NSEG; j++) {
            float h = 0.f;
            #pragma unroll
            for (int k = 0; k < 4; k++) {
                float b = S_ * xv[4*j+k];
                if (j == 0 && tid == 0 && k == 0) b = xv[0];
                h = fmaf(a, h, b);
            }
            float y = h, yp;
            yp = __shfl_up_sync(0xFFFFFFFFu, y, 1);  if (lane >= 1)  y = fmaf(a4,  yp, y);
            yp = __shfl_up_sync(0xFFFFFFFFu, y, 2);  if (lane >= 2)  y = fmaf(a8,  yp, y);
            yp = __shfl_up_sync(0xFFFFFFFFu, y, 4);  if (lane >= 4)  y = fmaf(a16, yp, y);
            yp = __shfl_up_sync(0xFFFFFFFFu, y, 8);  if (lane >= 8)  y = fmaf(a32, yp, y);
            yp = __shfl_up_sync(0xFFFFFFFFu, y, 16); if (lane >= 16) y = fmaf(a64, yp, y);
            P[j] = y;
            if (lane == 31) sT[j * 8 + warp] = y;
        }
        __syncthreads();

        // ---- middle scan, done redundantly by EVERY warp (no warp-0 bottleneck) ----
        float y = sT[lane], yp;
        yp = __shfl_up_sync(0xFFFFFFFFu, y, 1);  if (lane >= 1)  y = fmaf(a128,  yp, y);
        yp = __shfl_up_sync(0xFFFFFFFFu, y, 2);  if (lane >= 2)  y = fmaf(a256,  yp, y);
        yp = __shfl_up_sync(0xFFFFFFFFu, y, 4);  if (lane >= 4)  y = fmaf(a512,  yp, y);
        yp = __shfl_up_sync(0xFFFFFFFFu, y, 8);  if (lane >= 8)  y = fmaf(a1024, yp, y);
        yp = __shfl_up_sync(0xFFFFFFFFu, y, 16); if (lane >= 16) y = fmaf(a2048, yp, y);
        float e = __shfl_up_sync(0xFFFFFFFFu, y, 1);
        if (lane == 0) e = 0.f;                  // e[lane] = exclusive carry of chunk 'lane'
        __syncthreads();                         // sT free for next iteration

        // ---- pass 2: apply carries, seeded recurrence + pointwise PCEN, store ----
        #pragma unroll
        for (int j = 0; j < NSEG; j++) {
            float Cw = __shfl_sync(0xFFFFFFFFu, e, j * 8 + warp);   // this chunk's carry
            float E  = __shfl_up_sync(0xFFFFFFFFu, P[j], 1);        // lane-exclusive prefix
            if (lane == 0) E = 0.f;
            float sm = fmaf(A4L, Cw, E);

            float r[4];
            #pragma unroll
            for (int k = 0; k < 4; k++) {
                float xk = xv[4*j+k];
                float b = S_ * xk;
                if (j == 0 && tid == 0 && k == 0) b = xk;
                sm = fmaf(a, sm, b);
                float p = fex2(NALPHA * flg2(sm + EPSf));   // (sm+eps)^-0.98
                r[k] = fsqrt_approx(fmaf(xk, p, DELTA)) - DR;
            }

            int i = j * 1024 + tid * 4;
            if (i < T_LEN)
                *reinterpret_cast<float4*>(orow + i) = make_float4(r[0], r[1], r[2], r[3]);
        }
    }
}

extern "C" void kernel_launch(void* const* d_in, const int* in_sizes, int n_in,
                              void* d_out, int out_size)
{
    const float* x = (const float*)d_in[0];
    float* out = (float*)d_out;
    int rows = in_sizes[0] / T_LEN;   // 8192
    pcen_kernel<<<NBLK, THREADS>>>(x, out, rows);
}

// round 9
// speedup vs baseline: 1.0936x; 1.0885x over previous
#include <cuda_runtime.h>
#include <cuda_bf16.h>

#define T_LEN   4000
#define THREADS 256
#define NSEG    4       // 4 segments x 1024 = 4096 >= 4000

__device__ __forceinline__ float fsqrt_approx(float u) {
    float r; asm("sqrt.approx.f32 %0, %1;" : "=f"(r) : "f"(u)); return r;
}
__device__ __forceinline__ float flg2(float u) {
    float r; asm("lg2.approx.f32 %0, %1;" : "=f"(r) : "f"(u)); return r;
}
__device__ __forceinline__ float fex2(float u) {
    float r; asm("ex2.approx.f32 %0, %1;" : "=f"(r) : "f"(u)); return r;
}

__global__ __launch_bounds__(THREADS, 8)   // <=32 regs -> 64 warps/SM
void pcen_kernel(const float* __restrict__ x, float* __restrict__ out)
{
    __shared__ float sT[32];   // 128-element chunk totals (chain order c = j*8 + warp)

    const float a      = 0.975f;     // 1 - S
    const float S_     = 0.025f;
    const float NALPHA = -0.98f;
    const float DELTA  = 2.0f;
    const float EPSf   = 1e-6f;
    const float DR     = 1.41421356237309515f;  // sqrt(2)

    // compile-time powers of a
    const float a2 = a*a, a4 = a2*a2, a8 = a4*a4, a16 = a8*a8,
                a32 = a16*a16, a64 = a32*a32, a128 = a64*a64,
                a256 = a128*a128, a512 = a256*a256,
                a1024 = a512*a512, a2048 = a1024*a1024;

    const int tid  = threadIdx.x;
    const int lane = tid & 31, warp = tid >> 5;   // 8 warps
    const int row  = blockIdx.x;
    const float* __restrict__ xr   = x   + (size_t)row * T_LEN;
    float* __restrict__       orow = out + (size_t)row * T_LEN;

    // a^(4*lane), exact bit product
    float A4L = 1.0f;
    if (lane & 1)  A4L *= a4;
    if (lane & 2)  A4L *= a8;
    if (lane & 4)  A4L *= a16;
    if (lane & 8)  A4L *= a32;
    if (lane & 16) A4L *= a64;

    // ---- pass 1 (streaming): load float4, fold into h, discard ----
    // b[0] = x[0] (global init), b[t] = S*x[t] otherwise
    float P[NSEG];
    #pragma unroll
    for (int j = 0; j < NSEG; j++) {
        int i = j * 1024 + tid * 4;
        float4 t4 = make_float4(0.f, 0.f, 0.f, 0.f);
        if (i < T_LEN) t4 = *reinterpret_cast<const float4*>(xr + i);

        float h = (j == 0 && tid == 0) ? t4.x : S_ * t4.x;   // h = a*0 + b0
        h = fmaf(a, h, S_ * t4.y);
        h = fmaf(a, h, S_ * t4.z);
        h = fmaf(a, h, S_ * t4.w);

        float y = h, yp;
        yp = __shfl_up_sync(0xFFFFFFFFu, y, 1);  if (lane >= 1)  y = fmaf(a4,  yp, y);
        yp = __shfl_up_sync(0xFFFFFFFFu, y, 2);  if (lane >= 2)  y = fmaf(a8,  yp, y);
        yp = __shfl_up_sync(0xFFFFFFFFu, y, 4);  if (lane >= 4)  y = fmaf(a16, yp, y);
        yp = __shfl_up_sync(0xFFFFFFFFu, y, 8);  if (lane >= 8)  y = fmaf(a32, yp, y);
        yp = __shfl_up_sync(0xFFFFFFFFu, y, 16); if (lane >= 16) y = fmaf(a64, yp, y);
        P[j] = y;
        if (lane == 31) sT[j * 8 + warp] = y;   // 128-element chunk total
    }
    __syncthreads();

    // ---- middle scan over 32 chunks, redundantly in every warp ----
    float y = sT[lane], yp;
    yp = __shfl_up_sync(0xFFFFFFFFu, y, 1);  if (lane >= 1)  y = fmaf(a128,  yp, y);
    yp = __shfl_up_sync(0xFFFFFFFFu, y, 2);  if (lane >= 2)  y = fmaf(a256,  yp, y);
    yp = __shfl_up_sync(0xFFFFFFFFu, y, 4);  if (lane >= 4)  y = fmaf(a512,  yp, y);
    yp = __shfl_up_sync(0xFFFFFFFFu, y, 8);  if (lane >= 8)  y = fmaf(a1024, yp, y);
    yp = __shfl_up_sync(0xFFFFFFFFu, y, 16); if (lane >= 16) y = fmaf(a2048, yp, y);
    float e = __shfl_up_sync(0xFFFFFFFFu, y, 1);
    if (lane == 0) e = 0.f;                  // e[lane] = exclusive carry of chunk 'lane'

    // ---- pass 2: re-read x (L1 hit), seeded recurrence + PCEN, store ----
    #pragma unroll
    for (int j = 0; j < NSEG; j++) {
        float Cw = __shfl_sync(0xFFFFFFFFu, e, j * 8 + warp);   // this chunk's carry
        float E  = __shfl_up_sync(0xFFFFFFFFu, P[j], 1);        // lane-exclusive prefix
        if (lane == 0) E = 0.f;
        float sm = fmaf(A4L, Cw, E);

        int i = j * 1024 + tid * 4;
        if (i < T_LEN) {
            float4 t4 = *reinterpret_cast<const float4*>(xr + i);   // L1-resident

            float b0 = (j == 0 && tid == 0) ? t4.x : S_ * t4.x;
            sm = fmaf(a, sm, b0);
            float r0 = fsqrt_approx(fmaf(t4.x, fex2(NALPHA * flg2(sm + EPSf)), DELTA)) - DR;

            sm = fmaf(a, sm, S_ * t4.y);
            float r1 = fsqrt_approx(fmaf(t4.y, fex2(NALPHA * flg2(sm + EPSf)), DELTA)) - DR;

            sm = fmaf(a, sm, S_ * t4.z);
            float r2 = fsqrt_approx(fmaf(t4.z, fex2(NALPHA * flg2(sm + EPSf)), DELTA)) - DR;

            sm = fmaf(a, sm, S_ * t4.w);
            float r3 = fsqrt_approx(fmaf(t4.w, fex2(NALPHA * flg2(sm + EPSf)), DELTA)) - DR;

            *reinterpret_cast<float4*>(orow + i) = make_float4(r0, r1, r2, r3);
        }
    }
}

extern "C" void kernel_launch(void* const* d_in, const int* in_sizes, int n_in,
                              void* d_out, int out_size)
{
    const float* x = (const float*)d_in[0];
    float* out = (float*)d_out;
    int rows = in_sizes[0] / T_LEN;   // 8192
    pcen_kernel<<<rows, THREADS>>>(x, out);
}